// round 1
// baseline (speedup 1.0000x reference)
#include <cuda_runtime.h>
#include <math.h>

#define QN 4
#define BB 8
#define SS 1024
#define DD 768
#define NN 1024
#define HH 512
#define MM (BB*SS)      /* 8192 tokens */
#define DD2 (2*DD)      /* 1536 */

// Scratch (device globals; no runtime allocation allowed)
__device__ float g_res[MM*DD];      // residual          25 MB
__device__ float g_qout[MM*DD];     // quantized_out     25 MB
__device__ float g_h[MM*DD2];       // hidden scratch    50 MB (max 1536 cols)

// ---------------------------------------------------------------------------
__global__ void init_kernel(const float* __restrict__ x) {
    int i = blockIdx.x * blockDim.x + threadIdx.x;
    if (i < MM*DD) { g_res[i] = x[i]; g_qout[i] = 0.f; }
}

// ---------------------------------------------------------------------------
// C[M x Nc] = relu( bn( A[M x K] @ W[K x Nc] + b ) ), eval-mode BN per column.
// All dims divisible by tile sizes (M=8192, K in {512,768,1536}, Nc in {512,768,1024,1536}).
// 128x128 block tile, KT=8, 256 threads, 8x8 microtile (4+4 split layout).
__global__ __launch_bounds__(256, 2)
void gemm_bn_relu(const float* __restrict__ A, const float* __restrict__ W,
                  const float* __restrict__ b,  const float* __restrict__ g,
                  const float* __restrict__ be, const float* __restrict__ m,
                  const float* __restrict__ v,  float* __restrict__ C,
                  int K, int Nc)
{
    __shared__ float As[8][128];
    __shared__ float Bs[8][128];

    const int tid = threadIdx.x;
    const int tx = tid & 15;        // 0..15 -> column groups
    const int ty = tid >> 4;        // 0..15 -> row groups
    const int m0 = blockIdx.y * 128;
    const int n0 = blockIdx.x * 128;

    float acc[8][8];
#pragma unroll
    for (int i = 0; i < 8; i++)
#pragma unroll
        for (int j = 0; j < 8; j++) acc[i][j] = 0.f;

    // A-tile loader: thread -> row=tid>>1 (0..127), k-quad=(tid&1)*4
    const int arow = tid >> 1;
    const int akq  = (tid & 1) * 4;
    const float* Aptr = A + (long)(m0 + arow) * K + akq;
    // B-tile loader: thread -> k-row=tid>>5 (0..7), n-quad=(tid&31)*4
    const int brow = tid >> 5;
    const int bnq  = (tid & 31) * 4;
    const float* Wptr = W + (long)brow * Nc + n0 + bnq;

    for (int k0 = 0; k0 < K; k0 += 8) {
        float4 a4 = *(const float4*)(Aptr + k0);
        float4 b4 = *(const float4*)(Wptr + (long)k0 * Nc);
        As[akq + 0][arow] = a4.x;
        As[akq + 1][arow] = a4.y;
        As[akq + 2][arow] = a4.z;
        As[akq + 3][arow] = a4.w;
        *(float4*)&Bs[brow][bnq] = b4;
        __syncthreads();

#pragma unroll
        for (int kk = 0; kk < 8; kk++) {
            float a[8], bq[8];
            *(float4*)&a[0]  = *(const float4*)&As[kk][ty * 4];
            *(float4*)&a[4]  = *(const float4*)&As[kk][64 + ty * 4];
            *(float4*)&bq[0] = *(const float4*)&Bs[kk][tx * 4];
            *(float4*)&bq[4] = *(const float4*)&Bs[kk][64 + tx * 4];
#pragma unroll
            for (int i = 0; i < 8; i++)
#pragma unroll
                for (int j = 0; j < 8; j++)
                    acc[i][j] += a[i] * bq[j];
        }
        __syncthreads();
    }

    // Epilogue: out = relu(acc * s + off), s = g*rsqrt(v+eps), off = (b-m)*s + be
    float sc[8], of[8];
    int cidx[8];
#pragma unroll
    for (int j = 0; j < 8; j++) {
        int c = n0 + ((j < 4) ? (tx * 4 + j) : (64 + tx * 4 + (j - 4)));
        cidx[j] = c;
        float s = g[c] * rsqrtf(v[c] + 1e-5f);
        sc[j] = s;
        of[j] = (b[c] - m[c]) * s + be[c];
    }
#pragma unroll
    for (int i = 0; i < 8; i++) {
        int r = m0 + ((i < 4) ? (ty * 4 + i) : (64 + ty * 4 + (i - 4)));
        float4 o0, o1;
        o0.x = fmaxf(acc[i][0] * sc[0] + of[0], 0.f);
        o0.y = fmaxf(acc[i][1] * sc[1] + of[1], 0.f);
        o0.z = fmaxf(acc[i][2] * sc[2] + of[2], 0.f);
        o0.w = fmaxf(acc[i][3] * sc[3] + of[3], 0.f);
        o1.x = fmaxf(acc[i][4] * sc[4] + of[4], 0.f);
        o1.y = fmaxf(acc[i][5] * sc[5] + of[5], 0.f);
        o1.z = fmaxf(acc[i][6] * sc[6] + of[6], 0.f);
        o1.w = fmaxf(acc[i][7] * sc[7] + of[7], 0.f);
        *(float4*)&C[(long)r * Nc + cidx[0]] = o0;
        *(float4*)&C[(long)r * Nc + cidx[4]] = o1;
    }
}

// ---------------------------------------------------------------------------
// Per-token: softmax stats over N=1024 (entropy, latent), argmax(z+gumbel),
// codebook gather, residual/quantized_out update.
// grid = MM blocks, 256 threads.
__global__ void token_kernel(const float* __restrict__ z,
                             const float* __restrict__ gum,
                             const float* __restrict__ cb,
                             float* __restrict__ ent_out,
                             float* __restrict__ lat_out,
                             float* __restrict__ idx_out)
{
    const int t = blockIdx.x;
    const int tid = threadIdx.x;
    const float* zr = z + (long)t * NN;
    const float* gr = gum + (long)t * NN;

    __shared__ float sred[256];
    __shared__ float sval[256];
    __shared__ int   sidx[256];

    float zv[4];
    float lmax = -INFINITY;
    float amax = -INFINITY;
    int   aidx = 0x7fffffff;
#pragma unroll
    for (int j = 0; j < 4; j++) {
        int c = tid + 256 * j;
        float zz = zr[c];
        zv[j] = zz;
        lmax = fmaxf(lmax, zz);
        float lg = zz + gr[c];
        if (lg > amax) { amax = lg; aidx = c; }   // keeps lowest c within thread
    }

    sred[tid] = lmax; sval[tid] = amax; sidx[tid] = aidx;
    __syncthreads();
    for (int s = 128; s > 0; s >>= 1) {
        if (tid < s) {
            sred[tid] = fmaxf(sred[tid], sred[tid + s]);
            float v2 = sval[tid + s]; int i2 = sidx[tid + s];
            if (v2 > sval[tid] || (v2 == sval[tid] && i2 < sidx[tid])) {
                sval[tid] = v2; sidx[tid] = i2;
            }
        }
        __syncthreads();
    }
    const float zmax = sred[0];
    const int   idx  = sidx[0];
    __syncthreads();

    // sum of exp
    float se = 0.f;
#pragma unroll
    for (int j = 0; j < 4; j++) se += expf(zv[j] - zmax);
    sred[tid] = se;
    __syncthreads();
    for (int s = 128; s > 0; s >>= 1) {
        if (tid < s) sred[tid] += sred[tid + s];
        __syncthreads();
    }
    const float inv = 1.f / sred[0];
    __syncthreads();

    // entropy + latent
    float entp = 0.f;
#pragma unroll
    for (int j = 0; j < 4; j++) {
        int c = tid + 256 * j;
        float qy = expf(zv[j] - zmax) * inv;
        entp -= qy * logf(qy + 1e-10f);
        lat_out[(long)t * NN + c] = qy * logf(qy * 1024.f + 1e-10f);
    }
    sred[tid] = entp;
    __syncthreads();
    for (int s = 128; s > 0; s >>= 1) {
        if (tid < s) sred[tid] += sred[tid + s];
        __syncthreads();
    }
    if (tid == 0) {
        ent_out[t] = sred[0];
        idx_out[t] = (float)idx;
    }

    // z_q = codebook[idx] (straight-through one_hot == y_hard numerically)
    const float* cbr = cb + (long)idx * DD;
    float* rr = g_res  + (long)t * DD;
    float* qq = g_qout + (long)t * DD;
    for (int d = tid; d < DD; d += 256) {
        float cv = cbr[d];
        rr[d] -= cv;
        qq[d] += cv;
    }
}

// ---------------------------------------------------------------------------
extern "C" void kernel_launch(void* const* d_in, const int* in_sizes, int n_in,
                              void* d_out, int out_size)
{
    const float* x    = (const float*)d_in[0];
    const float* cb   = (const float*)d_in[1];
    const float* pW1  = (const float*)d_in[2];
    const float* pb1  = (const float*)d_in[3];
    const float* pg1  = (const float*)d_in[4];
    const float* pbe1 = (const float*)d_in[5];
    const float* pm1  = (const float*)d_in[6];
    const float* pv1  = (const float*)d_in[7];
    const float* pW2  = (const float*)d_in[8];
    const float* pb2  = (const float*)d_in[9];
    const float* pg2  = (const float*)d_in[10];
    const float* pbe2 = (const float*)d_in[11];
    const float* pm2  = (const float*)d_in[12];
    const float* pv2  = (const float*)d_in[13];
    const float* dW1  = (const float*)d_in[14];
    const float* db1  = (const float*)d_in[15];
    const float* dg1  = (const float*)d_in[16];
    const float* dbe1 = (const float*)d_in[17];
    const float* dm1  = (const float*)d_in[18];
    const float* dv1  = (const float*)d_in[19];
    const float* dW2  = (const float*)d_in[20];
    const float* db2  = (const float*)d_in[21];
    const float* dg2  = (const float*)d_in[22];
    const float* dbe2 = (const float*)d_in[23];
    const float* dm2  = (const float*)d_in[24];
    const float* dv2  = (const float*)d_in[25];
    const float* gum  = (const float*)d_in[26];

    float* out  = (float*)d_out;
    float* xhat = out;                                  // [MM, DD]
    float* ent  = xhat + (long)MM * DD;                 // [QN, MM]
    float* lat  = ent  + (long)QN * MM;                 // [QN, MM, NN]
    float* idxo = lat  + (long)QN * MM * NN;            // [QN, MM]
    float* zs   = idxo + (long)QN * MM;                 // [QN, MM, NN]

    float *res_p, *qout_p, *h_p;
    cudaGetSymbolAddress((void**)&res_p,  g_res);
    cudaGetSymbolAddress((void**)&qout_p, g_qout);
    cudaGetSymbolAddress((void**)&h_p,    g_h);

    init_kernel<<<(MM*DD + 255) / 256, 256>>>(x);

    for (int i = 0; i < QN; i++) {
        // h = blk(res, pW1[i], ...)   [8192x768]x[768x512]
        gemm_bn_relu<<<dim3(HH/128, MM/128), 256>>>(
            res_p, pW1 + (long)i*DD*HH,
            pb1 + i*HH, pg1 + i*HH, pbe1 + i*HH, pm1 + i*HH, pv1 + i*HH,
            h_p, DD, HH);
        // z = blk(h, pW2[i], ...)     [8192x512]x[512x1024]  -> zs output slice
        float* z_i = zs + (long)i * MM * NN;
        gemm_bn_relu<<<dim3(NN/128, MM/128), 256>>>(
            h_p, pW2 + (long)i*HH*NN,
            pb2 + i*NN, pg2 + i*NN, pbe2 + i*NN, pm2 + i*NN, pv2 + i*NN,
            z_i, HH, NN);
        // softmax stats, argmax, gather, residual update
        token_kernel<<<MM, 256>>>(
            z_i, gum + (long)i * MM * NN, cb + (long)i * NN * DD,
            ent + (long)i * MM, lat + (long)i * MM * NN, idxo + (long)i * MM);
    }

    // decoder: hidden = blk(qout, dW1...)  [8192x768]x[768x1536]
    gemm_bn_relu<<<dim3(DD2/128, MM/128), 256>>>(
        qout_p, dW1, db1, dg1, dbe1, dm1, dv1, h_p, DD, DD2);
    // xhat = blk(hidden, dW2...)           [8192x1536]x[1536x768]
    gemm_bn_relu<<<dim3(DD/128, MM/128), 256>>>(
        h_p, dW2, db2, dg2, dbe2, dm2, dv2, xhat, DD2, DD);
}

// round 3
// speedup vs baseline: 2.0940x; 2.0940x over previous
#include <cuda_runtime.h>
#include <cuda_bf16.h>
#include <math.h>
#include <stdint.h>

#define QN 4
#define DD 768
#define NN 1024
#define HH 512
#define MM 8192
#define DD2 1536

// ---------------- device scratch (no runtime allocation) -------------------
__device__ float g_res[MM*DD];
__device__ float g_qout[MM*DD];
__device__ __align__(128) __nv_bfloat16 g_Ahi[MM*DD];
__device__ __align__(128) __nv_bfloat16 g_Alo[MM*DD];
__device__ __align__(128) __nv_bfloat16 g_Hhi[MM*DD2];
__device__ __align__(128) __nv_bfloat16 g_Hlo[MM*DD2];
#define WT_TOTAL 6029312
__device__ __align__(128) __nv_bfloat16 g_Wthi[WT_TOTAL];
__device__ __align__(128) __nv_bfloat16 g_Wtlo[WT_TOTAL];

// ---------------- PTX helpers ----------------------------------------------
__device__ __forceinline__ uint32_t smem_u32(const void* p) {
    uint32_t a;
    asm("{ .reg .u64 t; cvta.to.shared.u64 t, %1; cvt.u32.u64 %0, t; }" : "=r"(a) : "l"(p));
    return a;
}
#define CP_ASYNC16(dst, src) \
    asm volatile("cp.async.cg.shared.global [%0], [%1], 16;\n" :: "r"(dst), "l"(src))
#define CP_COMMIT() asm volatile("cp.async.commit_group;\n" ::: "memory")
#define CP_WAIT(n)  asm volatile("cp.async.wait_group %0;\n" :: "n"(n) : "memory")

#define LDSM4(f, addr) \
    asm volatile("ldmatrix.sync.aligned.m8n8.x4.shared.b16 {%0,%1,%2,%3}, [%4];\n" \
        : "=r"((f)[0]), "=r"((f)[1]), "=r"((f)[2]), "=r"((f)[3]) : "r"(addr))

#define MMA16816(d, a, b0, b1) \
    asm volatile("mma.sync.aligned.m16n8k16.row.col.f32.bf16.bf16.f32 " \
        "{%0,%1,%2,%3}, {%4,%5,%6,%7}, {%8,%9}, {%0,%1,%2,%3};\n" \
        : "+f"((d)[0]), "+f"((d)[1]), "+f"((d)[2]), "+f"((d)[3]) \
        : "r"((a)[0]), "r"((a)[1]), "r"((a)[2]), "r"((a)[3]), "r"(b0), "r"(b1))

// ---------------- small kernels --------------------------------------------
__global__ void init_kernel(const float* __restrict__ x) {
    int i = blockIdx.x * blockDim.x + threadIdx.x;
    if (i < MM*DD) { g_res[i] = x[i]; g_qout[i] = 0.f; }
}

// fp32 -> (hi, lo) bf16 split, elementwise, float4-vectorized
__global__ void asplit(const float* __restrict__ A, __nv_bfloat16* __restrict__ hi,
                       __nv_bfloat16* __restrict__ lo, int n4) {
    int i = blockIdx.x * blockDim.x + threadIdx.x;
    if (i >= n4) return;
    float4 a = ((const float4*)A)[i];
    float av[4] = {a.x, a.y, a.z, a.w};
    __nv_bfloat16 h[4], l[4];
#pragma unroll
    for (int j = 0; j < 4; j++) {
        h[j] = __float2bfloat16(av[j]);
        l[j] = __float2bfloat16(av[j] - __bfloat162float(h[j]));
    }
    ((ushort4*)hi)[i] = make_ushort4(*(unsigned short*)&h[0], *(unsigned short*)&h[1],
                                     *(unsigned short*)&h[2], *(unsigned short*)&h[3]);
    ((ushort4*)lo)[i] = make_ushort4(*(unsigned short*)&l[0], *(unsigned short*)&l[1],
                                     *(unsigned short*)&l[2], *(unsigned short*)&l[3]);
}

// W[K,N] fp32 -> Wt_hi/lo[N,K] bf16 (tiled transpose + split)
__global__ void wsplit(const float* __restrict__ W, __nv_bfloat16* __restrict__ Thi,
                       __nv_bfloat16* __restrict__ Tlo, int K, int N) {
    __shared__ float t[32][33];
    int k0 = blockIdx.y * 32, n0 = blockIdx.x * 32;
    for (int i = threadIdx.y; i < 32; i += 8)
        t[i][threadIdx.x] = W[(size_t)(k0 + i) * N + n0 + threadIdx.x];
    __syncthreads();
    for (int i = threadIdx.y; i < 32; i += 8) {
        float val = t[threadIdx.x][i];
        __nv_bfloat16 h = __float2bfloat16(val);
        size_t o = (size_t)(n0 + i) * K + k0 + threadIdx.x;
        Thi[o] = h;
        Tlo[o] = __float2bfloat16(val - __bfloat162float(h));
    }
}

// ---------------- mma.sync split-bf16 GEMM ----------------------------------
// C[M,Nc] = relu(bn(A @ W)), A = Ahi+Alo [M,K] bf16 row-major,
// W^T = Whi+Wlo [Nc,K] bf16 row-major. 3 accumulation passes (hh, hl, lh).
// 128x128 CTA tile, BK=64, 3-stage cp.async pipeline, 256 threads (8 warps,
// each 64x32). SW128 swizzle, conflict-free ldmatrix.
// mode 0: fp32 out to Cf. mode 1: bf16 hi/lo split out to Chi/Clo.
#define GS_STAGE 32768            /* 16KB A + 16KB B per stage */
#define GS_SC    98304
#define SMEM_G   (98304 + 1024)

__global__ __launch_bounds__(256, 2)
void mma_gemm(const __nv_bfloat16* __restrict__ Ahi, const __nv_bfloat16* __restrict__ Alo,
              const __nv_bfloat16* __restrict__ Whi, const __nv_bfloat16* __restrict__ Wlo,
              const float* __restrict__ bb, const float* __restrict__ gg,
              const float* __restrict__ be, const float* __restrict__ mm_,
              const float* __restrict__ vv,
              float* __restrict__ Cf, __nv_bfloat16* __restrict__ Chi,
              __nv_bfloat16* __restrict__ Clo, int K, int mode)
{
    extern __shared__ __align__(1024) char smem[];
    const uint32_t sbase = smem_u32(smem);
    float* scp = (float*)(smem + GS_SC);
    float* ofp = scp + 128;
    const int tid = threadIdx.x;
    const int Nc = gridDim.x * 128;
    const int n0 = blockIdx.x * 128;
    const int m0 = blockIdx.y * 128;

    if (tid < 128) {
        int c = n0 + tid;
        float s = gg[c] * rsqrtf(vv[c] + 1e-5f);
        scp[tid] = s;
        ofp[tid] = (bb[c] - mm_[c]) * s + be[c];
    }

    const int lane = tid & 31, wid = tid >> 5;
    const int wm = (wid >> 2) << 6;     // 0 or 64
    const int wn = (wid & 3) << 5;      // 0,32,64,96

    float acc[4][4][4];
#pragma unroll
    for (int im = 0; im < 4; im++)
#pragma unroll
        for (int in = 0; in < 4; in++)
#pragma unroll
            for (int r = 0; r < 4; r++) acc[im][in][r] = 0.f;

    // ldmatrix address precompute
    uint32_t aoff[4]; int asw[4];
#pragma unroll
    for (int im = 0; im < 4; im++) {
        int r = wm + (im << 4) + (lane & 15);
        aoff[im] = (uint32_t)(r << 7);
        asw[im] = r & 7;
    }
    const int acb = lane >> 4;                        // 0..1
    uint32_t boff[2]; int bsw[2];
#pragma unroll
    for (int jn = 0; jn < 2; jn++) {
        int r = wn + (jn << 4) + (lane & 7) + (((lane >> 4) & 1) << 3);
        boff[jn] = (uint32_t)(r << 7);
        bsw[jn] = r & 7;
    }
    const int bcb = (lane >> 3) & 1;

    const int KC = K >> 6;
    const int NC = 3 * KC;

    // ---- loader -------------------------------------------------------------
    auto load_chunk = [&](int c, int s) {
        int pass = c / KC;
        int k0 = (c - pass * KC) << 6;
        const __nv_bfloat16* Ap = (pass == 2) ? Alo : Ahi;
        const __nv_bfloat16* Wp = (pass == 1) ? Wlo : Whi;
        uint32_t bA = sbase + s * GS_STAGE;
        uint32_t bB = bA + 16384;
#pragma unroll
        for (int j = 0; j < 4; j++) {
            int q = tid + (j << 8);
            int row = q >> 3, cc = q & 7;
            uint32_t sw = (uint32_t)(row << 7) + (uint32_t)((cc ^ (row & 7)) << 4);
            CP_ASYNC16(bA + sw, Ap + (size_t)(m0 + row) * K + k0 + (cc << 3));
            CP_ASYNC16(bB + sw, Wp + (size_t)(n0 + row) * K + k0 + (cc << 3));
        }
    };

    // prologue
    load_chunk(0, 0); CP_COMMIT();
    load_chunk(1, 1); CP_COMMIT();

    for (int c = 0; c < NC; c++) {
        __syncthreads();                    // all warps done with chunk c-1
        if (c + 2 < NC) load_chunk(c + 2, (c + 2) % 3);
        CP_COMMIT();
        CP_WAIT(2);                         // chunk c's data arrived (this thread)
        __syncthreads();                    // ... and all threads'

        uint32_t sA = sbase + (c % 3) * GS_STAGE;
        uint32_t sB = sA + 16384;
#pragma unroll
        for (int kk = 0; kk < 4; kk++) {
            uint32_t af[4][4], bf[2][4];
#pragma unroll
            for (int im = 0; im < 4; im++)
                LDSM4(af[im], sA + aoff[im] + (uint32_t)((((kk << 1) + acb) ^ asw[im]) << 4));
#pragma unroll
            for (int jn = 0; jn < 2; jn++)
                LDSM4(bf[jn], sB + boff[jn] + (uint32_t)((((kk << 1) + bcb) ^ bsw[jn]) << 4));
#pragma unroll
            for (int im = 0; im < 4; im++) {
#pragma unroll
                for (int in = 0; in < 4; in++) {
                    const uint32_t* bp = bf[in >> 1];
                    if (in & 1) MMA16816(acc[im][in], af[im], bp[2], bp[3]);
                    else        MMA16816(acc[im][in], af[im], bp[0], bp[1]);
                }
            }
        }
    }

    // ---- epilogue: BN + ReLU ------------------------------------------------
    const int rbase = m0 + wm + (lane >> 2);
    const int clbase = wn + ((lane & 3) << 1);
#pragma unroll
    for (int im = 0; im < 4; im++) {
#pragma unroll
        for (int in = 0; in < 4; in++) {
            int row = rbase + (im << 4);
            int cl = clbase + (in << 3);
            float s0 = scp[cl], s1 = scp[cl + 1];
            float o0 = ofp[cl], o1 = ofp[cl + 1];
            float v0 = fmaxf(acc[im][in][0] * s0 + o0, 0.f);
            float v1 = fmaxf(acc[im][in][1] * s1 + o1, 0.f);
            float v2 = fmaxf(acc[im][in][2] * s0 + o0, 0.f);
            float v3 = fmaxf(acc[im][in][3] * s1 + o1, 0.f);
            size_t p0 = (size_t)row * Nc + n0 + cl;
            size_t p1 = (size_t)(row + 8) * Nc + n0 + cl;
            if (mode == 0) {
                float2 w0; w0.x = v0; w0.y = v1;
                float2 w1; w1.x = v2; w1.y = v3;
                *(float2*)&Cf[p0] = w0;
                *(float2*)&Cf[p1] = w1;
            } else {
                __nv_bfloat16 h0 = __float2bfloat16(v0);
                __nv_bfloat16 h1 = __float2bfloat16(v1);
                __nv_bfloat16 h2 = __float2bfloat16(v2);
                __nv_bfloat16 h3 = __float2bfloat16(v3);
                __nv_bfloat162 hp0; hp0.x = h0; hp0.y = h1;
                __nv_bfloat162 hp1; hp1.x = h2; hp1.y = h3;
                __nv_bfloat162 lp0, lp1;
                lp0.x = __float2bfloat16(v0 - __bfloat162float(h0));
                lp0.y = __float2bfloat16(v1 - __bfloat162float(h1));
                lp1.x = __float2bfloat16(v2 - __bfloat162float(h2));
                lp1.y = __float2bfloat16(v3 - __bfloat162float(h3));
                *(__nv_bfloat162*)&Chi[p0] = hp0;
                *(__nv_bfloat162*)&Chi[p1] = hp1;
                *(__nv_bfloat162*)&Clo[p0] = lp0;
                *(__nv_bfloat162*)&Clo[p1] = lp1;
            }
        }
    }
}

// ---------------- token kernel ----------------------------------------------
__global__ void token_kernel(const float* __restrict__ z,
                             const float* __restrict__ gum,
                             const float* __restrict__ cb,
                             float* __restrict__ ent_out,
                             float* __restrict__ lat_out,
                             float* __restrict__ idx_out)
{
    const int t = blockIdx.x;
    const int tid = threadIdx.x;
    const float* zr = z + (size_t)t * NN;
    const float* gr = gum + (size_t)t * NN;

    __shared__ float sred[256];
    __shared__ float sval[256];
    __shared__ int   sidx[256];

    float zv[4];
    float lmax = -INFINITY;
    float amax = -INFINITY;
    int   aidx = 0x7fffffff;
#pragma unroll
    for (int j = 0; j < 4; j++) {
        int c = tid + 256 * j;
        float zz = zr[c];
        zv[j] = zz;
        lmax = fmaxf(lmax, zz);
        float lg = zz + gr[c];
        if (lg > amax) { amax = lg; aidx = c; }
    }

    sred[tid] = lmax; sval[tid] = amax; sidx[tid] = aidx;
    __syncthreads();
    for (int s = 128; s > 0; s >>= 1) {
        if (tid < s) {
            sred[tid] = fmaxf(sred[tid], sred[tid + s]);
            float v2 = sval[tid + s]; int i2 = sidx[tid + s];
            if (v2 > sval[tid] || (v2 == sval[tid] && i2 < sidx[tid])) {
                sval[tid] = v2; sidx[tid] = i2;
            }
        }
        __syncthreads();
    }
    const float zmax = sred[0];
    const int   idx  = sidx[0];
    __syncthreads();

    float se = 0.f;
#pragma unroll
    for (int j = 0; j < 4; j++) se += expf(zv[j] - zmax);
    sred[tid] = se;
    __syncthreads();
    for (int s = 128; s > 0; s >>= 1) {
        if (tid < s) sred[tid] += sred[tid + s];
        __syncthreads();
    }
    const float inv = 1.f / sred[0];
    __syncthreads();

    float entp = 0.f;
#pragma unroll
    for (int j = 0; j < 4; j++) {
        int c = tid + 256 * j;
        float qy = expf(zv[j] - zmax) * inv;
        entp -= qy * logf(qy + 1e-10f);
        lat_out[(size_t)t * NN + c] = qy * logf(qy * 1024.f + 1e-10f);
    }
    sred[tid] = entp;
    __syncthreads();
    for (int s = 128; s > 0; s >>= 1) {
        if (tid < s) sred[tid] += sred[tid + s];
        __syncthreads();
    }
    if (tid == 0) {
        ent_out[t] = sred[0];
        idx_out[t] = (float)idx;
    }

    const float* cbr = cb + (size_t)idx * DD;
    float* rr = g_res  + (size_t)t * DD;
    float* qq = g_qout + (size_t)t * DD;
    for (int d = tid; d < DD; d += 256) {
        float cv = cbr[d];
        rr[d] -= cv;
        qq[d] += cv;
    }
}

// ---------------- host launch ----------------------------------------------
extern "C" void kernel_launch(void* const* d_in, const int* in_sizes, int n_in,
                              void* d_out, int out_size)
{
    const float* x    = (const float*)d_in[0];
    const float* cb   = (const float*)d_in[1];
    const float* pW1  = (const float*)d_in[2];
    const float* pb1  = (const float*)d_in[3];
    const float* pg1  = (const float*)d_in[4];
    const float* pbe1 = (const float*)d_in[5];
    const float* pm1  = (const float*)d_in[6];
    const float* pv1  = (const float*)d_in[7];
    const float* pW2  = (const float*)d_in[8];
    const float* pb2  = (const float*)d_in[9];
    const float* pg2  = (const float*)d_in[10];
    const float* pbe2 = (const float*)d_in[11];
    const float* pm2  = (const float*)d_in[12];
    const float* pv2  = (const float*)d_in[13];
    const float* dW1  = (const float*)d_in[14];
    const float* db1  = (const float*)d_in[15];
    const float* dg1  = (const float*)d_in[16];
    const float* dbe1 = (const float*)d_in[17];
    const float* dm1  = (const float*)d_in[18];
    const float* dv1  = (const float*)d_in[19];
    const float* dW2  = (const float*)d_in[20];
    const float* db2  = (const float*)d_in[21];
    const float* dg2  = (const float*)d_in[22];
    const float* dbe2 = (const float*)d_in[23];
    const float* dm2  = (const float*)d_in[24];
    const float* dv2  = (const float*)d_in[25];
    const float* gum  = (const float*)d_in[26];

    float* out  = (float*)d_out;
    float* xhat = out;                                  // [MM, DD]
    float* ent  = xhat + (size_t)MM * DD;               // [QN, MM]
    float* lat  = ent  + (size_t)QN * MM;               // [QN, MM, NN]
    float* idxo = lat  + (size_t)QN * MM * NN;          // [QN, MM]
    float* zs   = idxo + (size_t)QN * MM;               // [QN, MM, NN]

    float *res_p, *qout_p;
    __nv_bfloat16 *Ahi, *Alo, *Hhi, *Hlo, *Wthi, *Wtlo;
    cudaGetSymbolAddress((void**)&res_p,  g_res);
    cudaGetSymbolAddress((void**)&qout_p, g_qout);
    cudaGetSymbolAddress((void**)&Ahi,  g_Ahi);
    cudaGetSymbolAddress((void**)&Alo,  g_Alo);
    cudaGetSymbolAddress((void**)&Hhi,  g_Hhi);
    cudaGetSymbolAddress((void**)&Hlo,  g_Hlo);
    cudaGetSymbolAddress((void**)&Wthi, g_Wthi);
    cudaGetSymbolAddress((void**)&Wtlo, g_Wtlo);

    cudaFuncSetAttribute(mma_gemm, cudaFuncAttributeMaxDynamicSharedMemorySize, SMEM_G);

    // weight transpose+split offsets
    const size_t O_P1 = 0;                      // 4 x 512*768
    const size_t SZ_P1 = (size_t)HH * DD;
    const size_t O_P2 = 4 * SZ_P1;
    const size_t SZ_P2 = (size_t)NN * HH;
    const size_t O_D1 = O_P2 + 4 * SZ_P2;
    const size_t SZ_D1 = (size_t)DD2 * DD;
    const size_t O_D2 = O_D1 + SZ_D1;

    init_kernel<<<(MM*DD + 255) / 256, 256>>>(x);

    dim3 wtb(32, 8);
    for (int i = 0; i < QN; i++) {
        wsplit<<<dim3(HH/32, DD/32), wtb>>>(pW1 + (size_t)i*DD*HH,
                                            Wthi + O_P1 + i*SZ_P1, Wtlo + O_P1 + i*SZ_P1, DD, HH);
        wsplit<<<dim3(NN/32, HH/32), wtb>>>(pW2 + (size_t)i*HH*NN,
                                            Wthi + O_P2 + i*SZ_P2, Wtlo + O_P2 + i*SZ_P2, HH, NN);
    }
    wsplit<<<dim3(DD2/32, DD/32), wtb>>>(dW1, Wthi + O_D1, Wtlo + O_D1, DD, DD2);
    wsplit<<<dim3(DD/32, DD2/32), wtb>>>(dW2, Wthi + O_D2, Wtlo + O_D2, DD2, DD);

    for (int i = 0; i < QN; i++) {
        asplit<<<(MM*DD/4 + 255)/256, 256>>>(res_p, Ahi, Alo, MM*DD/4);
        // h = blk(res @ pW1) -> bf16 split [8192 x 512]
        mma_gemm<<<dim3(HH/128, MM/128), 256, SMEM_G>>>(
            Ahi, Alo, Wthi + O_P1 + i*SZ_P1, Wtlo + O_P1 + i*SZ_P1,
            pb1 + i*HH, pg1 + i*HH, pbe1 + i*HH, pm1 + i*HH, pv1 + i*HH,
            nullptr, Hhi, Hlo, DD, 1);
        // z = blk(h @ pW2) -> fp32 zs slice [8192 x 1024]
        float* z_i = zs + (size_t)i * MM * NN;
        mma_gemm<<<dim3(NN/128, MM/128), 256, SMEM_G>>>(
            Hhi, Hlo, Wthi + O_P2 + i*SZ_P2, Wtlo + O_P2 + i*SZ_P2,
            pb2 + i*NN, pg2 + i*NN, pbe2 + i*NN, pm2 + i*NN, pv2 + i*NN,
            z_i, nullptr, nullptr, HH, 0);
        token_kernel<<<MM, 256>>>(
            z_i, gum + (size_t)i * MM * NN, cb + (size_t)i * NN * DD,
            ent + (size_t)i * MM, lat + (size_t)i * MM * NN, idxo + (size_t)i * MM);
    }

    // decoder
    asplit<<<(MM*DD/4 + 255)/256, 256>>>(qout_p, Ahi, Alo, MM*DD/4);
    mma_gemm<<<dim3(DD2/128, MM/128), 256, SMEM_G>>>(
        Ahi, Alo, Wthi + O_D1, Wtlo + O_D1,
        db1, dg1, dbe1, dm1, dv1,
        nullptr, Hhi, Hlo, DD, 1);
    mma_gemm<<<dim3(DD/128, MM/128), 256, SMEM_G>>>(
        Hhi, Hlo, Wthi + O_D2, Wtlo + O_D2,
        db2, dg2, dbe2, dm2, dv2,
        xhat, nullptr, nullptr, DD2, 0);
}

// round 4
// speedup vs baseline: 2.4185x; 1.1550x over previous
#include <cuda_runtime.h>
#include <cuda_bf16.h>
#include <math.h>
#include <stdint.h>

#define QN 4
#define DD 768
#define NN 1024
#define HH 512
#define MM 8192
#define DD2 1536

// ---------------- device scratch (no runtime allocation) -------------------
__device__ float g_res[MM*DD];
__device__ float g_qout[MM*DD];
__device__ __align__(128) __nv_bfloat16 g_Ahi[MM*DD];
__device__ __align__(128) __nv_bfloat16 g_Alo[MM*DD];
__device__ __align__(128) __nv_bfloat16 g_Hhi[MM*DD2];
__device__ __align__(128) __nv_bfloat16 g_Hlo[MM*DD2];
#define WT_TOTAL 6029312
__device__ __align__(128) __nv_bfloat16 g_Wthi[WT_TOTAL];
__device__ __align__(128) __nv_bfloat16 g_Wtlo[WT_TOTAL];

// ---------------- PTX helpers ----------------------------------------------
__device__ __forceinline__ uint32_t smem_u32(const void* p) {
    uint32_t a;
    asm("{ .reg .u64 t; cvta.to.shared.u64 t, %1; cvt.u32.u64 %0, t; }" : "=r"(a) : "l"(p));
    return a;
}
#define CP_ASYNC16(dst, src) \
    asm volatile("cp.async.cg.shared.global [%0], [%1], 16;\n" :: "r"(dst), "l"(src))
#define CP_COMMIT() asm volatile("cp.async.commit_group;\n" ::: "memory")
#define CP_WAIT(n)  asm volatile("cp.async.wait_group %0;\n" :: "n"(n) : "memory")

#define LDSM4(f, addr) \
    asm volatile("ldmatrix.sync.aligned.m8n8.x4.shared.b16 {%0,%1,%2,%3}, [%4];\n" \
        : "=r"((f)[0]), "=r"((f)[1]), "=r"((f)[2]), "=r"((f)[3]) : "r"(addr))

#define MMA16816(d, a, b0, b1) \
    asm volatile("mma.sync.aligned.m16n8k16.row.col.f32.bf16.bf16.f32 " \
        "{%0,%1,%2,%3}, {%4,%5,%6,%7}, {%8,%9}, {%0,%1,%2,%3};\n" \
        : "+f"((d)[0]), "+f"((d)[1]), "+f"((d)[2]), "+f"((d)[3]) \
        : "r"((a)[0]), "r"((a)[1]), "r"((a)[2]), "r"((a)[3]), "r"(b0), "r"(b1))

// ---------------- small kernels --------------------------------------------
// init: res=x, qout=0, and split(x) -> Ahi/Alo
__global__ void init_kernel(const float* __restrict__ x) {
    int i = blockIdx.x * blockDim.x + threadIdx.x;
    if (i >= MM*DD/4) return;
    float4 a = ((const float4*)x)[i];
    ((float4*)g_res)[i] = a;
    float4 z4; z4.x = z4.y = z4.z = z4.w = 0.f;
    ((float4*)g_qout)[i] = z4;
    float av[4] = {a.x, a.y, a.z, a.w};
    __nv_bfloat16 h[4], l[4];
#pragma unroll
    for (int j = 0; j < 4; j++) {
        h[j] = __float2bfloat16(av[j]);
        l[j] = __float2bfloat16(av[j] - __bfloat162float(h[j]));
    }
    ((ushort4*)g_Ahi)[i] = make_ushort4(*(unsigned short*)&h[0], *(unsigned short*)&h[1],
                                        *(unsigned short*)&h[2], *(unsigned short*)&h[3]);
    ((ushort4*)g_Alo)[i] = make_ushort4(*(unsigned short*)&l[0], *(unsigned short*)&l[1],
                                        *(unsigned short*)&l[2], *(unsigned short*)&l[3]);
}

// W[K,N] fp32 -> Wt_hi/lo[N,K] bf16 (tiled transpose + split)
__global__ void wsplit(const float* __restrict__ W, __nv_bfloat16* __restrict__ Thi,
                       __nv_bfloat16* __restrict__ Tlo, int K, int N) {
    __shared__ float t[32][33];
    int k0 = blockIdx.y * 32, n0 = blockIdx.x * 32;
    for (int i = threadIdx.y; i < 32; i += 8)
        t[i][threadIdx.x] = W[(size_t)(k0 + i) * N + n0 + threadIdx.x];
    __syncthreads();
    for (int i = threadIdx.y; i < 32; i += 8) {
        float val = t[threadIdx.x][i];
        __nv_bfloat16 h = __float2bfloat16(val);
        size_t o = (size_t)(n0 + i) * K + k0 + threadIdx.x;
        Thi[o] = h;
        Tlo[o] = __float2bfloat16(val - __bfloat162float(h));
    }
}

// ---------------- mma.sync split-bf16 GEMM, interleaved hi/lo ---------------
// C[M,Nc] = relu(bn(A @ W)). Per K-chunk (BK=64) load Ahi|Alo and Whi|Wlo once
// (256B rows: [hi 128B | lo 128B], SW128 swizzle per 128B atom) and accumulate
// hh + h*lo + lo*h into the same fp32 acc. 128x128 CTA tile, 3-stage cp.async,
// 256 threads (8 warps x 64x32 warp tile), 1 CTA/SM.
// mode 0: fp32 out to Cf. mode 1: bf16 hi/lo split out to Chi/Clo.
#define GS_STAGE 65536            /* 32KB A(hi|lo) + 32KB W(hi|lo) */
#define GS_SC    196608
#define SMEM_G   (196608 + 1024)

__global__ __launch_bounds__(256, 1)
void mma_gemm(const __nv_bfloat16* __restrict__ Ahi, const __nv_bfloat16* __restrict__ Alo,
              const __nv_bfloat16* __restrict__ Whi, const __nv_bfloat16* __restrict__ Wlo,
              const float* __restrict__ bb, const float* __restrict__ gg,
              const float* __restrict__ be, const float* __restrict__ mm_,
              const float* __restrict__ vv,
              float* __restrict__ Cf, __nv_bfloat16* __restrict__ Chi,
              __nv_bfloat16* __restrict__ Clo, int K, int mode)
{
    extern __shared__ __align__(1024) char smem[];
    const uint32_t sbase = smem_u32(smem);
    float* scp = (float*)(smem + GS_SC);
    float* ofp = scp + 128;
    const int tid = threadIdx.x;
    const int Nc = gridDim.x * 128;
    const int n0 = blockIdx.x * 128;
    const int m0 = blockIdx.y * 128;

    if (tid < 128) {
        int c = n0 + tid;
        float s = gg[c] * rsqrtf(vv[c] + 1e-5f);
        scp[tid] = s;
        ofp[tid] = (bb[c] - mm_[c]) * s + be[c];
    }

    const int lane = tid & 31, wid = tid >> 5;
    const int wm = (wid >> 2) << 6;     // 0 or 64
    const int wn = (wid & 3) << 5;      // 0,32,64,96

    float acc[4][4][4];
#pragma unroll
    for (int im = 0; im < 4; im++)
#pragma unroll
        for (int in = 0; in < 4; in++)
#pragma unroll
            for (int r = 0; r < 4; r++) acc[im][in][r] = 0.f;

    // ldmatrix address precompute (row stride 256B)
    uint32_t aoff[4]; int asw[4];
#pragma unroll
    for (int im = 0; im < 4; im++) {
        int r = wm + (im << 4) + (lane & 15);
        aoff[im] = (uint32_t)(r << 8);
        asw[im] = r & 7;
    }
    const int acb = lane >> 4;
    uint32_t boff[2]; int bsw[2];
#pragma unroll
    for (int jn = 0; jn < 2; jn++) {
        int r = wn + (jn << 4) + (lane & 7) + (((lane >> 4) & 1) << 3);
        boff[jn] = (uint32_t)(r << 8);
        bsw[jn] = r & 7;
    }
    const int bcb = (lane >> 3) & 1;

    const int NC = K >> 6;

    // loader: per thread, 16B chunk index constant (tid&15): half = hi/lo select
    const int lrow0 = tid >> 4;          // 0..15
    const int lc16  = tid & 15;
    const int lhalf = lc16 >> 3;         // 0=hi, 1=lo
    const int lcc   = lc16 & 7;
    const __nv_bfloat16* Asrc = lhalf ? Alo : Ahi;
    const __nv_bfloat16* Wsrc = lhalf ? Wlo : Whi;
    const uint32_t lhoff = (uint32_t)(lhalf << 7);

    auto load_chunk = [&](int c, int s) {
        int k0 = c << 6;
        uint32_t bA = sbase + s * GS_STAGE;
        uint32_t bB = bA + 32768;
#pragma unroll
        for (int j = 0; j < 8; j++) {
            int row = lrow0 + (j << 4);
            uint32_t sw = (uint32_t)(row << 8) + lhoff + (uint32_t)((lcc ^ (row & 7)) << 4);
            CP_ASYNC16(bA + sw, Asrc + (size_t)(m0 + row) * K + k0 + (lcc << 3));
            CP_ASYNC16(bB + sw, Wsrc + (size_t)(n0 + row) * K + k0 + (lcc << 3));
        }
    };

    load_chunk(0, 0); CP_COMMIT();
    load_chunk(1, 1); CP_COMMIT();

    for (int c = 0; c < NC; c++) {
        __syncthreads();
        if (c + 2 < NC) load_chunk(c + 2, (c + 2) % 3);
        CP_COMMIT();
        CP_WAIT(2);
        __syncthreads();

        uint32_t sA = sbase + (c % 3) * GS_STAGE;
        uint32_t sB = sA + 32768;
#pragma unroll
        for (int kk = 0; kk < 4; kk++) {
            uint32_t afh[4][4], afl[4][4], bfh[2][4], bfl[2][4];
            const int sela = (kk << 1) + acb;
            const int selb = (kk << 1) + bcb;
#pragma unroll
            for (int im = 0; im < 4; im++) {
                uint32_t base = sA + aoff[im] + (uint32_t)((sela ^ asw[im]) << 4);
                LDSM4(afh[im], base);
                LDSM4(afl[im], base + 128);
            }
#pragma unroll
            for (int jn = 0; jn < 2; jn++) {
                uint32_t base = sB + boff[jn] + (uint32_t)((selb ^ bsw[jn]) << 4);
                LDSM4(bfh[jn], base);
                LDSM4(bfl[jn], base + 128);
            }
            // hh
#pragma unroll
            for (int im = 0; im < 4; im++)
#pragma unroll
                for (int in = 0; in < 4; in++) {
                    const uint32_t* bp = bfh[in >> 1];
                    if (in & 1) MMA16816(acc[im][in], afh[im], bp[2], bp[3]);
                    else        MMA16816(acc[im][in], afh[im], bp[0], bp[1]);
                }
            // hi * lo
#pragma unroll
            for (int im = 0; im < 4; im++)
#pragma unroll
                for (int in = 0; in < 4; in++) {
                    const uint32_t* bp = bfl[in >> 1];
                    if (in & 1) MMA16816(acc[im][in], afh[im], bp[2], bp[3]);
                    else        MMA16816(acc[im][in], afh[im], bp[0], bp[1]);
                }
            // lo * hi
#pragma unroll
            for (int im = 0; im < 4; im++)
#pragma unroll
                for (int in = 0; in < 4; in++) {
                    const uint32_t* bp = bfh[in >> 1];
                    if (in & 1) MMA16816(acc[im][in], afl[im], bp[2], bp[3]);
                    else        MMA16816(acc[im][in], afl[im], bp[0], bp[1]);
                }
        }
    }

    // ---- epilogue: BN + ReLU ------------------------------------------------
    const int rbase = m0 + wm + (lane >> 2);
    const int clbase = wn + ((lane & 3) << 1);
#pragma unroll
    for (int im = 0; im < 4; im++) {
#pragma unroll
        for (int in = 0; in < 4; in++) {
            int row = rbase + (im << 4);
            int cl = clbase + (in << 3);
            float s0 = scp[cl], s1 = scp[cl + 1];
            float o0 = ofp[cl], o1 = ofp[cl + 1];
            float v0 = fmaxf(acc[im][in][0] * s0 + o0, 0.f);
            float v1 = fmaxf(acc[im][in][1] * s1 + o1, 0.f);
            float v2 = fmaxf(acc[im][in][2] * s0 + o0, 0.f);
            float v3 = fmaxf(acc[im][in][3] * s1 + o1, 0.f);
            size_t p0 = (size_t)row * Nc + n0 + cl;
            size_t p1 = (size_t)(row + 8) * Nc + n0 + cl;
            if (mode == 0) {
                float2 w0; w0.x = v0; w0.y = v1;
                float2 w1; w1.x = v2; w1.y = v3;
                *(float2*)&Cf[p0] = w0;
                *(float2*)&Cf[p1] = w1;
            } else {
                __nv_bfloat16 h0 = __float2bfloat16(v0);
                __nv_bfloat16 h1 = __float2bfloat16(v1);
                __nv_bfloat16 h2 = __float2bfloat16(v2);
                __nv_bfloat16 h3 = __float2bfloat16(v3);
                __nv_bfloat162 hp0; hp0.x = h0; hp0.y = h1;
                __nv_bfloat162 hp1; hp1.x = h2; hp1.y = h3;
                __nv_bfloat162 lp0, lp1;
                lp0.x = __float2bfloat16(v0 - __bfloat162float(h0));
                lp0.y = __float2bfloat16(v1 - __bfloat162float(h1));
                lp1.x = __float2bfloat16(v2 - __bfloat162float(h2));
                lp1.y = __float2bfloat16(v3 - __bfloat162float(h3));
                *(__nv_bfloat162*)&Chi[p0] = hp0;
                *(__nv_bfloat162*)&Chi[p1] = hp1;
                *(__nv_bfloat162*)&Clo[p0] = lp0;
                *(__nv_bfloat162*)&Clo[p1] = lp1;
            }
        }
    }
}

// ---------------- token kernel (shuffle reductions + fused split) -----------
// split_mode: 0 -> write split(updated res) to g_Ahi/g_Alo
//             1 -> write split(updated qout) to g_Ahi/g_Alo (last stage)
__global__ void token_kernel(const float* __restrict__ z,
                             const float* __restrict__ gum,
                             const float* __restrict__ cb,
                             float* __restrict__ ent_out,
                             float* __restrict__ lat_out,
                             float* __restrict__ idx_out,
                             int split_mode)
{
    const int t = blockIdx.x;
    const int tid = threadIdx.x;
    const int lane = tid & 31, wrp = tid >> 5;
    const float* zr = z + (size_t)t * NN;
    const float* gr = gum + (size_t)t * NN;

    __shared__ float swa[8];
    __shared__ float swb[8];
    __shared__ int   swi[8];

    float zv[4];
    float lmax = -INFINITY;
    float amax = -INFINITY;
    int   aidx = 0x7fffffff;
#pragma unroll
    for (int j = 0; j < 4; j++) {
        int c = tid + 256 * j;
        float zz = zr[c];
        zv[j] = zz;
        lmax = fmaxf(lmax, zz);
        float lg = zz + gr[c];
        if (lg > amax) { amax = lg; aidx = c; }
    }
    // warp reduce: max and argmax
#pragma unroll
    for (int o = 16; o > 0; o >>= 1) {
        lmax = fmaxf(lmax, __shfl_xor_sync(0xffffffffu, lmax, o));
        float ov = __shfl_xor_sync(0xffffffffu, amax, o);
        int   oi = __shfl_xor_sync(0xffffffffu, aidx, o);
        if (ov > amax || (ov == amax && oi < aidx)) { amax = ov; aidx = oi; }
    }
    if (lane == 0) { swa[wrp] = lmax; swb[wrp] = amax; swi[wrp] = aidx; }
    __syncthreads();
    float zmax = swa[0];
    float bv = swb[0]; int bi = swi[0];
#pragma unroll
    for (int w = 1; w < 8; w++) {
        zmax = fmaxf(zmax, swa[w]);
        float ov = swb[w]; int oi = swi[w];
        if (ov > bv || (ov == bv && oi < bi)) { bv = ov; bi = oi; }
    }
    const int idx = bi;
    __syncthreads();

    // sum of exp
    float se = 0.f;
#pragma unroll
    for (int j = 0; j < 4; j++) se += expf(zv[j] - zmax);
#pragma unroll
    for (int o = 16; o > 0; o >>= 1) se += __shfl_xor_sync(0xffffffffu, se, o);
    if (lane == 0) swa[wrp] = se;
    __syncthreads();
    float tot = 0.f;
#pragma unroll
    for (int w = 0; w < 8; w++) tot += swa[w];
    const float inv = 1.f / tot;

    // entropy + latent
    float entp = 0.f;
#pragma unroll
    for (int j = 0; j < 4; j++) {
        int c = tid + 256 * j;
        float qy = expf(zv[j] - zmax) * inv;
        entp -= qy * logf(qy + 1e-10f);
        lat_out[(size_t)t * NN + c] = qy * logf(qy * 1024.f + 1e-10f);
    }
#pragma unroll
    for (int o = 16; o > 0; o >>= 1) entp += __shfl_xor_sync(0xffffffffu, entp, o);
    __syncthreads();
    if (lane == 0) swb[wrp] = entp;
    __syncthreads();
    if (tid == 0) {
        float e = 0.f;
#pragma unroll
        for (int w = 0; w < 8; w++) e += swb[w];
        ent_out[t] = e;
        idx_out[t] = (float)idx;
    }

    // z_q = codebook[idx]; update res/qout and emit split of the one we need next
    const float* cbr = cb + (size_t)idx * DD;
    float* rr = g_res  + (size_t)t * DD;
    float* qq = g_qout + (size_t)t * DD;
    __nv_bfloat16* oh = g_Ahi + (size_t)t * DD;
    __nv_bfloat16* ol = g_Alo + (size_t)t * DD;
#pragma unroll
    for (int j = 0; j < 3; j++) {
        int d = tid + 256 * j;
        float cv = cbr[d];
        float r = rr[d] - cv; rr[d] = r;
        float q = qq[d] + cv; qq[d] = q;
        float sv = split_mode ? q : r;
        __nv_bfloat16 h = __float2bfloat16(sv);
        oh[d] = h;
        ol[d] = __float2bfloat16(sv - __bfloat162float(h));
    }
}

// ---------------- host launch ----------------------------------------------
extern "C" void kernel_launch(void* const* d_in, const int* in_sizes, int n_in,
                              void* d_out, int out_size)
{
    const float* x    = (const float*)d_in[0];
    const float* cb   = (const float*)d_in[1];
    const float* pW1  = (const float*)d_in[2];
    const float* pb1  = (const float*)d_in[3];
    const float* pg1  = (const float*)d_in[4];
    const float* pbe1 = (const float*)d_in[5];
    const float* pm1  = (const float*)d_in[6];
    const float* pv1  = (const float*)d_in[7];
    const float* pW2  = (const float*)d_in[8];
    const float* pb2  = (const float*)d_in[9];
    const float* pg2  = (const float*)d_in[10];
    const float* pbe2 = (const float*)d_in[11];
    const float* pm2  = (const float*)d_in[12];
    const float* pv2  = (const float*)d_in[13];
    const float* dW1  = (const float*)d_in[14];
    const float* db1  = (const float*)d_in[15];
    const float* dg1  = (const float*)d_in[16];
    const float* dbe1 = (const float*)d_in[17];
    const float* dm1  = (const float*)d_in[18];
    const float* dv1  = (const float*)d_in[19];
    const float* dW2  = (const float*)d_in[20];
    const float* db2  = (const float*)d_in[21];
    const float* dg2  = (const float*)d_in[22];
    const float* dbe2 = (const float*)d_in[23];
    const float* dm2  = (const float*)d_in[24];
    const float* dv2  = (const float*)d_in[25];
    const float* gum  = (const float*)d_in[26];

    float* out  = (float*)d_out;
    float* xhat = out;                                  // [MM, DD]
    float* ent  = xhat + (size_t)MM * DD;               // [QN, MM]
    float* lat  = ent  + (size_t)QN * MM;               // [QN, MM, NN]
    float* idxo = lat  + (size_t)QN * MM * NN;          // [QN, MM]
    float* zs   = idxo + (size_t)QN * MM;               // [QN, MM, NN]

    __nv_bfloat16 *Ahi, *Alo, *Hhi, *Hlo, *Wthi, *Wtlo;
    cudaGetSymbolAddress((void**)&Ahi,  g_Ahi);
    cudaGetSymbolAddress((void**)&Alo,  g_Alo);
    cudaGetSymbolAddress((void**)&Hhi,  g_Hhi);
    cudaGetSymbolAddress((void**)&Hlo,  g_Hlo);
    cudaGetSymbolAddress((void**)&Wthi, g_Wthi);
    cudaGetSymbolAddress((void**)&Wtlo, g_Wtlo);

    cudaFuncSetAttribute(mma_gemm, cudaFuncAttributeMaxDynamicSharedMemorySize, SMEM_G);

    const size_t O_P1 = 0;
    const size_t SZ_P1 = (size_t)HH * DD;
    const size_t O_P2 = 4 * SZ_P1;
    const size_t SZ_P2 = (size_t)NN * HH;
    const size_t O_D1 = O_P2 + 4 * SZ_P2;
    const size_t SZ_D1 = (size_t)DD2 * DD;
    const size_t O_D2 = O_D1 + SZ_D1;

    init_kernel<<<(MM*DD/4 + 255) / 256, 256>>>(x);

    dim3 wtb(32, 8);
    for (int i = 0; i < QN; i++) {
        wsplit<<<dim3(HH/32, DD/32), wtb>>>(pW1 + (size_t)i*DD*HH,
                                            Wthi + O_P1 + i*SZ_P1, Wtlo + O_P1 + i*SZ_P1, DD, HH);
        wsplit<<<dim3(NN/32, HH/32), wtb>>>(pW2 + (size_t)i*HH*NN,
                                            Wthi + O_P2 + i*SZ_P2, Wtlo + O_P2 + i*SZ_P2, HH, NN);
    }
    wsplit<<<dim3(DD2/32, DD/32), wtb>>>(dW1, Wthi + O_D1, Wtlo + O_D1, DD, DD2);
    wsplit<<<dim3(DD/32, DD2/32), wtb>>>(dW2, Wthi + O_D2, Wtlo + O_D2, DD2, DD);

    for (int i = 0; i < QN; i++) {
        // h = blk(res @ pW1) -> bf16 split [8192 x 512]
        mma_gemm<<<dim3(HH/128, MM/128), 256, SMEM_G>>>(
            Ahi, Alo, Wthi + O_P1 + i*SZ_P1, Wtlo + O_P1 + i*SZ_P1,
            pb1 + i*HH, pg1 + i*HH, pbe1 + i*HH, pm1 + i*HH, pv1 + i*HH,
            nullptr, Hhi, Hlo, DD, 1);
        // z = blk(h @ pW2) -> fp32 zs slice [8192 x 1024]
        float* z_i = zs + (size_t)i * MM * NN;
        mma_gemm<<<dim3(NN/128, MM/128), 256, SMEM_G>>>(
            Hhi, Hlo, Wthi + O_P2 + i*SZ_P2, Wtlo + O_P2 + i*SZ_P2,
            pb2 + i*NN, pg2 + i*NN, pbe2 + i*NN, pm2 + i*NN, pv2 + i*NN,
            z_i, nullptr, nullptr, HH, 0);
        token_kernel<<<MM, 256>>>(
            z_i, gum + (size_t)i * MM * NN, cb + (size_t)i * NN * DD,
            ent + (size_t)i * MM, lat + (size_t)i * MM * NN, idxo + (size_t)i * MM,
            (i == QN - 1) ? 1 : 0);
    }

    // decoder (Ahi/Alo now hold split(qout) from last token_kernel)
    mma_gemm<<<dim3(DD2/128, MM/128), 256, SMEM_G>>>(
        Ahi, Alo, Wthi + O_D1, Wtlo + O_D1,
        db1, dg1, dbe1, dm1, dv1,
        nullptr, Hhi, Hlo, DD, 1);
    mma_gemm<<<dim3(DD/128, MM/128), 256, SMEM_G>>>(
        Hhi, Hlo, Wthi + O_D2, Wtlo + O_D2,
        db2, dg2, dbe2, dm2, dv2,
        xhat, nullptr, nullptr, DD2, 0);
}